// round 9
// baseline (speedup 1.0000x reference)
#include <cuda_runtime.h>
#include <math.h>
#include <stdint.h>

// Shapes: B=4, T=8, RES=32, C=128 -> L=8192, M=32768 rows
// branch0: Hsp=32, Wsp=4 ; branch1: Hsp=4, Wsp=32 ; win=512, nh=4, hd=16

#define M_TOK 32768

// round fp32 -> tf32 (rna), keep fp32 container
__device__ __forceinline__ float tf32r(float x) {
    uint32_t u;
    asm("cvt.rna.tf32.f32 %0, %1;" : "=r"(u) : "f"(x));
    return __uint_as_float(u);
}
__device__ __forceinline__ uint32_t fu(float x) { return __float_as_uint(x); }
// D(16x8,f32) += A(16x8,tf32 row) * B(8x8,tf32 col)
__device__ __forceinline__ void mma8(float c[4],
                                     uint32_t a0, uint32_t a1, uint32_t a2,
                                     uint32_t a3, uint32_t b0, uint32_t b1) {
    asm("mma.sync.aligned.m16n8k8.row.col.f32.tf32.tf32.f32 "
        "{%0,%1,%2,%3}, {%4,%5,%6,%7}, {%8,%9}, {%0,%1,%2,%3};"
        : "+f"(c[0]), "+f"(c[1]), "+f"(c[2]), "+f"(c[3])
        : "r"(a0), "r"(a1), "r"(a2), "r"(a3), "r"(b0), "r"(b1));
}

// Scratch (static device arrays; no runtime allocation)
__device__ float g_norm[M_TOK * 128];
__device__ float g_qkv [M_TOK * 384];
__device__ float g_att [M_TOK * 128];
__device__ float g_hid [M_TOK * 512];

// ---------------------------------------------------------------------------
// LayerNorm: one warp per 128-channel row
// ---------------------------------------------------------------------------
__global__ void __launch_bounds__(256) ln_kernel(
    const float* __restrict__ x, const float* __restrict__ w,
    const float* __restrict__ b, float* __restrict__ out)
{
    int lane = threadIdx.x & 31;
    int row  = blockIdx.x * 8 + (threadIdx.x >> 5);
    const float4 v = *(const float4*)(x + (size_t)row * 128 + lane * 4);
    float s = v.x + v.y + v.z + v.w;
    #pragma unroll
    for (int o = 16; o; o >>= 1) s += __shfl_xor_sync(0xffffffffu, s, o);
    float mu = s * (1.0f / 128.0f);
    float dx = v.x - mu, dy = v.y - mu, dz = v.z - mu, dw = v.w - mu;
    float sq = dx * dx + dy * dy + dz * dz + dw * dw;
    #pragma unroll
    for (int o = 16; o; o >>= 1) sq += __shfl_xor_sync(0xffffffffu, sq, o);
    float r = rsqrtf(sq * (1.0f / 128.0f) + 1e-5f);
    float4 wv = *(const float4*)(w + lane * 4);
    float4 bv = *(const float4*)(b + lane * 4);
    float4 o4;
    o4.x = dx * r * wv.x + bv.x;
    o4.y = dy * r * wv.y + bv.y;
    o4.z = dz * r * wv.z + bv.z;
    o4.w = dw * r * wv.w + bv.w;
    *(float4*)(out + (size_t)row * 128 + lane * 4) = o4;
}

// ---------------------------------------------------------------------------
// tf32 tensor-core GEMM, double-buffered SMEM.
// CTA 128x64, 8 warps (4x2), warp 32x32 = 2x4 m16n8k8 frags, BK=32.
// ---------------------------------------------------------------------------
template <bool GELU>
__global__ void __launch_bounds__(256) mma_gemm(
    const float* __restrict__ A, const float* __restrict__ W,
    const float* __restrict__ bias, const float* __restrict__ res,
    float* __restrict__ out, int N, int K)
{
    extern __shared__ float gsm[];
    float* sA = gsm;            // [2][128][36]
    float* sW = gsm + 9216;     // [2][64][36]

    const int tid  = threadIdx.x;
    const int m0   = blockIdx.y << 7, n0 = blockIdx.x << 6;
    const int warp = tid >> 5, lane = tid & 31;
    const int g    = lane >> 2, tig = lane & 3;
    const int wm   = warp >> 1, wn = warp & 1;

    float acc[2][4][4];
    #pragma unroll
    for (int mi = 0; mi < 2; mi++)
        #pragma unroll
        for (int ni = 0; ni < 4; ni++)
            #pragma unroll
            for (int q = 0; q < 4; q++) acc[mi][ni][q] = 0.f;

    const int srow = tid >> 3;        // 0..31
    const int skq  = (tid & 7) << 2;  // 0,4,...,28

    float4 ra[4], rw[2];
    #pragma unroll
    for (int p = 0; p < 4; p++)
        ra[p] = *(const float4*)(A + (size_t)(m0 + srow + (p << 5)) * K + skq);
    #pragma unroll
    for (int p = 0; p < 2; p++)
        rw[p] = *(const float4*)(W + (size_t)(n0 + srow + (p << 5)) * K + skq);

    // stage 0
    #pragma unroll
    for (int p = 0; p < 4; p++) {
        int base = (srow + (p << 5)) * 36 + skq;
        sA[base + 0] = tf32r(ra[p].x); sA[base + 1] = tf32r(ra[p].y);
        sA[base + 2] = tf32r(ra[p].z); sA[base + 3] = tf32r(ra[p].w);
    }
    #pragma unroll
    for (int p = 0; p < 2; p++) {
        int base = (srow + (p << 5)) * 36 + skq;
        sW[base + 0] = tf32r(rw[p].x); sW[base + 1] = tf32r(rw[p].y);
        sW[base + 2] = tf32r(rw[p].z); sW[base + 3] = tf32r(rw[p].w);
    }
    __syncthreads();

    int s = 0;
    for (int k0 = 0; k0 < K; k0 += 32) {
        const bool more = (k0 + 32 < K);
        if (more) {
            #pragma unroll
            for (int p = 0; p < 4; p++)
                ra[p] = *(const float4*)(A + (size_t)(m0 + srow + (p << 5)) * K
                                           + k0 + 32 + skq);
            #pragma unroll
            for (int p = 0; p < 2; p++)
                rw[p] = *(const float4*)(W + (size_t)(n0 + srow + (p << 5)) * K
                                           + k0 + 32 + skq);
        }
        const float* cA = sA + s * 4608;
        const float* cW = sW + s * 2304;
        #pragma unroll
        for (int k8 = 0; k8 < 32; k8 += 8) {
            uint32_t bf[4][2];
            #pragma unroll
            for (int ni = 0; ni < 4; ni++) {
                int n = (wn << 5) + (ni << 3) + g;
                bf[ni][0] = fu(cW[n * 36 + k8 + tig]);
                bf[ni][1] = fu(cW[n * 36 + k8 + tig + 4]);
            }
            #pragma unroll
            for (int mi = 0; mi < 2; mi++) {
                int m = (wm << 5) + (mi << 4);
                uint32_t a0 = fu(cA[(m + g) * 36 + k8 + tig]);
                uint32_t a1 = fu(cA[(m + g + 8) * 36 + k8 + tig]);
                uint32_t a2 = fu(cA[(m + g) * 36 + k8 + tig + 4]);
                uint32_t a3 = fu(cA[(m + g + 8) * 36 + k8 + tig + 4]);
                #pragma unroll
                for (int ni = 0; ni < 4; ni++)
                    mma8(acc[mi][ni], a0, a1, a2, a3, bf[ni][0], bf[ni][1]);
            }
        }
        if (more) {
            float* nA = sA + (s ^ 1) * 4608;
            float* nW = sW + (s ^ 1) * 2304;
            #pragma unroll
            for (int p = 0; p < 4; p++) {
                int base = (srow + (p << 5)) * 36 + skq;
                nA[base + 0] = tf32r(ra[p].x); nA[base + 1] = tf32r(ra[p].y);
                nA[base + 2] = tf32r(ra[p].z); nA[base + 3] = tf32r(ra[p].w);
            }
            #pragma unroll
            for (int p = 0; p < 2; p++) {
                int base = (srow + (p << 5)) * 36 + skq;
                nW[base + 0] = tf32r(rw[p].x); nW[base + 1] = tf32r(rw[p].y);
                nW[base + 2] = tf32r(rw[p].z); nW[base + 3] = tf32r(rw[p].w);
            }
        }
        __syncthreads();
        s ^= 1;
    }

    #pragma unroll
    for (int mi = 0; mi < 2; mi++) {
        int r0 = m0 + (wm << 5) + (mi << 4) + g;
        int r1 = r0 + 8;
        #pragma unroll
        for (int ni = 0; ni < 4; ni++) {
            int col = n0 + (wn << 5) + (ni << 3) + (tig << 1);
            float b0 = 0.f, b1 = 0.f;
            if (bias) {
                float2 bb = *(const float2*)(bias + col);
                b0 = bb.x; b1 = bb.y;
            }
            float v00 = acc[mi][ni][0] + b0;
            float v01 = acc[mi][ni][1] + b1;
            float v10 = acc[mi][ni][2] + b0;
            float v11 = acc[mi][ni][3] + b1;
            if (GELU) {
                v00 = 0.5f * v00 * (1.0f + erff(v00 * 0.70710678118654752f));
                v01 = 0.5f * v01 * (1.0f + erff(v01 * 0.70710678118654752f));
                v10 = 0.5f * v10 * (1.0f + erff(v10 * 0.70710678118654752f));
                v11 = 0.5f * v11 * (1.0f + erff(v11 * 0.70710678118654752f));
            }
            size_t o0 = (size_t)r0 * N + col;
            size_t o1 = (size_t)r1 * N + col;
            if (res) {
                float2 q0 = *(const float2*)(res + o0);
                float2 q1 = *(const float2*)(res + o1);
                v00 += q0.x; v01 += q0.y;
                v10 += q1.x; v11 += q1.y;
            }
            float2 w0 = {v00, v01};
            float2 w1 = {v10, v11};
            *(float2*)(out + o0) = w0;
            *(float2*)(out + o1) = w1;
        }
    }
}

// ---------------------------------------------------------------------------
// Tensor-core attention + fused LePE. One CTA per (branch, window, head).
// Warp owns 64 Q-rows; loop over 16-key blocks: QK^T mma -> exp in regs ->
// shuffle-transpose P -> P*V mma. O staged to SMEM, then LePE + writeout.
// ---------------------------------------------------------------------------
__global__ void __launch_bounds__(256, 2) attn_kernel(
    const float* __restrict__ qkv,
    const float* __restrict__ cw0, const float* __restrict__ cb0,
    const float* __restrict__ cw1, const float* __restrict__ cb1,
    float* __restrict__ att)
{
    extern __shared__ float dsm[];
    float* sK = dsm;                   // 512 x pitch20 (tf32)
    float* sV = dsm + 512 * 20;        // 512 x 16 (raw fp32)
    float* sQ = sV + 512 * 16;         // 512 x 16 (tf32, prescaled) -> later O
    __shared__ float sCW[27 * 16];
    __shared__ float sCB[16];

    int bid = blockIdx.x;
    int br  = bid >> 8;
    int rem = bid & 255;
    int w   = rem >> 2;
    int n   = rem & 3;
    int b   = w >> 4;
    int tb  = (w >> 3) & 1;
    int hw  = w & 7;
    int tid = threadIdx.x;

    auto tok = [&](int p) -> int {
        int ts = p >> 7, r2 = p & 127;
        if (br == 0) {
            int hs = r2 >> 2, ws = r2 & 3;
            return ((tb * 4 + ts) << 10) + (hs << 5) + (hw << 2) + ws;
        } else {
            int hs = r2 >> 5, ws = r2 & 31;
            return ((tb * 4 + ts) << 10) + (((hw << 2) + hs) << 5) + ws;
        }
    };

    int cq = br * 64 + n * 16;
    int rowbase = b * 8192;

    // stage K (pitch 20, tf32), V (pitch 16, raw), Q (pitch 16, tf32*0.25)
    for (int idx = tid; idx < 2048; idx += 256) {
        int p = idx >> 2, c4 = (idx & 3) << 2;
        const float* base = qkv + (size_t)(rowbase + tok(p)) * 384;
        float4 kq = *(const float4*)(base + 128 + cq + c4);
        float* kd = sK + p * 20 + c4;
        kd[0] = tf32r(kq.x); kd[1] = tf32r(kq.y);
        kd[2] = tf32r(kq.z); kd[3] = tf32r(kq.w);
        *(float4*)(sV + p * 16 + c4) = *(const float4*)(base + 256 + cq + c4);
        float4 qq = *(const float4*)(base + cq + c4);
        float* qd = sQ + p * 16 + c4;
        qd[0] = tf32r(qq.x * 0.25f); qd[1] = tf32r(qq.y * 0.25f);
        qd[2] = tf32r(qq.z * 0.25f); qd[3] = tf32r(qq.w * 0.25f);
    }
    {
        const float* cw = br ? cw1 : cw0;
        for (int idx = tid; idx < 432; idx += 256) {
            int d = idx / 27, k = idx - d * 27;
            sCW[k * 16 + d] = cw[(n * 16 + d) * 27 + k];
        }
        if (tid < 16) sCB[tid] = (br ? cb1 : cb0)[n * 16 + tid];
    }
    __syncthreads();

    const int lane = tid & 31, warp = tid >> 5;
    const int g = lane >> 2, tig = lane & 3;
    const int qbase = warp << 6;

    // Q fragments (persist)
    uint32_t qf[4][2][4];
    #pragma unroll
    for (int mi = 0; mi < 4; mi++)
        #pragma unroll
        for (int kt = 0; kt < 2; kt++) {
            int r0 = (qbase + (mi << 4) + g) * 16 + (kt << 3) + tig;
            qf[mi][kt][0] = fu(sQ[r0]);
            qf[mi][kt][1] = fu(sQ[r0 + 128]);
            qf[mi][kt][2] = fu(sQ[r0 + 4]);
            qf[mi][kt][3] = fu(sQ[r0 + 132]);
        }

    float acco[4][2][4];
    #pragma unroll
    for (int mi = 0; mi < 4; mi++)
        #pragma unroll
        for (int nt = 0; nt < 2; nt++)
            #pragma unroll
            for (int q = 0; q < 4; q++) acco[mi][nt][q] = 0.f;
    float rs[4][2];
    #pragma unroll
    for (int mi = 0; mi < 4; mi++) { rs[mi][0] = 0.f; rs[mi][1] = 0.f; }

    for (int j0 = 0; j0 < 512; j0 += 16) {
        float sc[4][2][4];
        #pragma unroll
        for (int mi = 0; mi < 4; mi++)
            #pragma unroll
            for (int nt = 0; nt < 2; nt++)
                #pragma unroll
                for (int q = 0; q < 4; q++) sc[mi][nt][q] = 0.f;

        // scores = Q K^T
        #pragma unroll
        for (int nt = 0; nt < 2; nt++) {
            int krow = (j0 + (nt << 3) + g) * 20;
            #pragma unroll
            for (int kt = 0; kt < 2; kt++) {
                uint32_t b0 = fu(sK[krow + (kt << 3) + tig]);
                uint32_t b1 = fu(sK[krow + (kt << 3) + tig + 4]);
                #pragma unroll
                for (int mi = 0; mi < 4; mi++)
                    mma8(sc[mi][nt], qf[mi][kt][0], qf[mi][kt][1],
                         qf[mi][kt][2], qf[mi][kt][3], b0, b1);
            }
        }
        // exp + rowsum (no max-sub: |score| small)
        #pragma unroll
        for (int mi = 0; mi < 4; mi++)
            #pragma unroll
            for (int nt = 0; nt < 2; nt++) {
                float e0 = __expf(sc[mi][nt][0]);
                float e1 = __expf(sc[mi][nt][1]);
                float e2 = __expf(sc[mi][nt][2]);
                float e3 = __expf(sc[mi][nt][3]);
                sc[mi][nt][0] = e0; sc[mi][nt][1] = e1;
                sc[mi][nt][2] = e2; sc[mi][nt][3] = e3;
                rs[mi][0] += e0 + e1;
                rs[mi][1] += e2 + e3;
            }
        // O += P V  (P transposed to A-frags via quad shuffles)
        const int srcl = (lane & ~3) | (tig >> 1);
        const bool odd = tig & 1;
        #pragma unroll
        for (int ktp = 0; ktp < 2; ktp++) {
            uint32_t pa[4][4];
            #pragma unroll
            for (int mi = 0; mi < 4; mi++) {
                float e0 = sc[mi][ktp][0], e1 = sc[mi][ktp][1];
                float e2 = sc[mi][ktp][2], e3 = sc[mi][ktp][3];
                float t0 = __shfl_sync(0xffffffffu, e0, srcl);
                float t1 = __shfl_sync(0xffffffffu, e1, srcl);
                float t2 = __shfl_sync(0xffffffffu, e2, srcl);
                float t3 = __shfl_sync(0xffffffffu, e3, srcl);
                float u0 = __shfl_sync(0xffffffffu, e0, srcl + 2);
                float u1 = __shfl_sync(0xffffffffu, e1, srcl + 2);
                float u2 = __shfl_sync(0xffffffffu, e2, srcl + 2);
                float u3 = __shfl_sync(0xffffffffu, e3, srcl + 2);
                pa[mi][0] = fu(odd ? t1 : t0);   // P[g][tig]
                pa[mi][1] = fu(odd ? t3 : t2);   // P[g+8][tig]
                pa[mi][2] = fu(odd ? u1 : u0);   // P[g][tig+4]
                pa[mi][3] = fu(odd ? u3 : u2);   // P[g+8][tig+4]
            }
            #pragma unroll
            for (int nt = 0; nt < 2; nt++) {
                uint32_t vb0 = fu(sV[(j0 + (ktp << 3) + tig) * 16
                                     + (nt << 3) + g]);
                uint32_t vb1 = fu(sV[(j0 + (ktp << 3) + tig + 4) * 16
                                     + (nt << 3) + g]);
                #pragma unroll
                for (int mi = 0; mi < 4; mi++)
                    mma8(acco[mi][nt], pa[mi][0], pa[mi][1],
                         pa[mi][2], pa[mi][3], vb0, vb1);
            }
        }
    }

    // finalize rowsums across the quad (lanes share g, tig varies)
    #pragma unroll
    for (int mi = 0; mi < 4; mi++) {
        #pragma unroll
        for (int r = 0; r < 2; r++) {
            float v = rs[mi][r];
            v += __shfl_xor_sync(0xffffffffu, v, 1);
            v += __shfl_xor_sync(0xffffffffu, v, 2);
            rs[mi][r] = v;
        }
    }

    // stage O (divided by rowsum) into sQ (all warps done reading Q)
    __syncthreads();
    #pragma unroll
    for (int mi = 0; mi < 4; mi++) {
        float iv0 = 1.0f / rs[mi][0];
        float iv1 = 1.0f / rs[mi][1];
        int row0 = qbase + (mi << 4) + g;
        #pragma unroll
        for (int nt = 0; nt < 2; nt++) {
            int a0 = row0 * 16 + (nt << 3) + (tig << 1);
            float2 lo = {acco[mi][nt][0] * iv0, acco[mi][nt][1] * iv0};
            float2 hi = {acco[mi][nt][2] * iv1, acco[mi][nt][3] * iv1};
            *(float2*)(sQ + a0) = lo;
            *(float2*)(sQ + a0 + 128) = hi;
        }
    }
    __syncthreads();

    // LePE + writeout: 2 rows per thread, O read from sQ, V from sV
    int Hsp = br ? 4 : 32;
    int Wsp = br ? 32 : 4;

    auto write_row = [&](int p) {
        int ltok = tok(p);
        int ts = p >> 7, r2 = p & 127;
        int hs = br ? (r2 >> 5) : (r2 >> 2);
        int ws = r2 & (Wsp - 1);
        float lep[16];
        #pragma unroll
        for (int d = 0; d < 16; d++) lep[d] = sCB[d];
        #pragma unroll
        for (int kt = 0; kt < 3; kt++) {
            int t2 = ts + kt - 1;
            if ((unsigned)t2 >= 4u) continue;
            #pragma unroll
            for (int kh = 0; kh < 3; kh++) {
                int h2 = hs + kh - 1;
                if ((unsigned)h2 >= (unsigned)Hsp) continue;
                #pragma unroll
                for (int kw = 0; kw < 3; kw++) {
                    int w2 = ws + kw - 1;
                    if ((unsigned)w2 >= (unsigned)Wsp) continue;
                    int pp = (t2 * Hsp + h2) * Wsp + w2;
                    int kidx = kt * 9 + kh * 3 + kw;
                    const float4* wr4 = (const float4*)&sCW[kidx * 16];
                    const float4* vr4 = (const float4*)&sV[pp * 16];
                    #pragma unroll
                    for (int d4 = 0; d4 < 4; d4++) {
                        float4 wv = wr4[d4];
                        float4 vv = vr4[d4];
                        lep[d4*4+0] = fmaf(wv.x, vv.x, lep[d4*4+0]);
                        lep[d4*4+1] = fmaf(wv.y, vv.y, lep[d4*4+1]);
                        lep[d4*4+2] = fmaf(wv.z, vv.z, lep[d4*4+2]);
                        lep[d4*4+3] = fmaf(wv.w, vv.w, lep[d4*4+3]);
                    }
                }
            }
        }
        float* op = att + (size_t)(rowbase + ltok) * 128 + cq;
        const float4* ov = (const float4*)(sQ + p * 16);
        #pragma unroll
        for (int d4 = 0; d4 < 4; d4++) {
            float4 a = ov[d4];
            float4 o;
            o.x = a.x + lep[d4*4+0];
            o.y = a.y + lep[d4*4+1];
            o.z = a.z + lep[d4*4+2];
            o.w = a.w + lep[d4*4+3];
            *(float4*)(op + d4 * 4) = o;
        }
    };
    write_row(tid);
    write_row(tid + 256);
}

// ---------------------------------------------------------------------------
// Launch sequence
// ---------------------------------------------------------------------------
extern "C" void kernel_launch(void* const* d_in, const int* in_sizes, int n_in,
                              void* d_out, int out_size)
{
    const float* x    = (const float*)d_in[0];
    const float* n1w  = (const float*)d_in[1];
    const float* n1b  = (const float*)d_in[2];
    const float* qkvw = (const float*)d_in[3];
    const float* cw0  = (const float*)d_in[4];
    const float* cb0  = (const float*)d_in[5];
    const float* cw1  = (const float*)d_in[6];
    const float* cb1  = (const float*)d_in[7];
    const float* pw   = (const float*)d_in[8];
    const float* pb   = (const float*)d_in[9];
    const float* n2w  = (const float*)d_in[10];
    const float* n2b  = (const float*)d_in[11];
    const float* f1w  = (const float*)d_in[12];
    const float* f1b  = (const float*)d_in[13];
    const float* f2w  = (const float*)d_in[14];
    const float* f2b  = (const float*)d_in[15];
    float* out = (float*)d_out;

    float *pnorm, *pqkv, *patt, *phid;
    cudaGetSymbolAddress((void**)&pnorm, g_norm);
    cudaGetSymbolAddress((void**)&pqkv,  g_qkv);
    cudaGetSymbolAddress((void**)&patt,  g_att);
    cudaGetSymbolAddress((void**)&phid,  g_hid);

    const int ATTN_SMEM = (512 * 20 + 512 * 16 + 512 * 16) * 4;  // 106496
    const int GEMM_SMEM = (2 * 128 * 36 + 2 * 64 * 36) * 4;      // 55296
    cudaFuncSetAttribute(attn_kernel,
                         cudaFuncAttributeMaxDynamicSharedMemorySize, ATTN_SMEM);
    cudaFuncSetAttribute(mma_gemm<false>,
                         cudaFuncAttributeMaxDynamicSharedMemorySize, GEMM_SMEM);
    cudaFuncSetAttribute(mma_gemm<true>,
                         cudaFuncAttributeMaxDynamicSharedMemorySize, GEMM_SMEM);

    // 1) LN1
    ln_kernel<<<4096, 256>>>(x, n1w, n1b, pnorm);
    // 2) qkv = LN1(x) @ qkv_w^T   (M x 384)
    mma_gemm<false><<<dim3(6, 256), 256, GEMM_SMEM>>>(pnorm, qkvw, nullptr,
                                                      nullptr, pqkv, 384, 128);
    // 3) windowed attention + LePE, both branches
    attn_kernel<<<512, 256, ATTN_SMEM>>>(pqkv, cw0, cb0, cw1, cb1, patt);
    // 4) x2 = x + att @ proj_w^T + proj_b  -> d_out
    mma_gemm<false><<<dim3(2, 256), 256, GEMM_SMEM>>>(patt, pw, pb, x, out,
                                                      128, 128);
    // 5) LN2
    ln_kernel<<<4096, 256>>>(out, n2w, n2b, pnorm);
    // 6) hid = gelu(LN2 @ fc1_w^T + fc1_b)  (M x 512)
    mma_gemm<true><<<dim3(8, 256), 256, GEMM_SMEM>>>(pnorm, f1w, f1b, nullptr,
                                                     phid, 512, 128);
    // 7) out = x2 + hid @ fc2_w^T + fc2_b
    mma_gemm<false><<<dim3(2, 256), 256, GEMM_SMEM>>>(phid, f2w, f2b, out, out,
                                                      128, 512);
}

// round 11
// speedup vs baseline: 1.6088x; 1.6088x over previous
#include <cuda_runtime.h>
#include <math.h>
#include <stdint.h>

// Shapes: B=4, T=8, RES=32, C=128 -> L=8192, M=32768 rows
// branch0: Hsp=32, Wsp=4 ; branch1: Hsp=4, Wsp=32 ; win=512, nh=4, hd=16

#define M_TOK 32768

__device__ __forceinline__ uint32_t fu(float x) { return __float_as_uint(x); }

// D(16x8,f32) += A(16x8,tf32 row) * B(8x8,tf32 col); raw fp32 bits in (HW truncates)
__device__ __forceinline__ void mma8(float c[4],
                                     uint32_t a0, uint32_t a1, uint32_t a2,
                                     uint32_t a3, uint32_t b0, uint32_t b1) {
    asm("mma.sync.aligned.m16n8k8.row.col.f32.tf32.tf32.f32 "
        "{%0,%1,%2,%3}, {%4,%5,%6,%7}, {%8,%9}, {%0,%1,%2,%3};"
        : "+f"(c[0]), "+f"(c[1]), "+f"(c[2]), "+f"(c[3])
        : "r"(a0), "r"(a1), "r"(a2), "r"(a3), "r"(b0), "r"(b1));
}

__device__ __forceinline__ void cp16(float* dst, const float* src) {
    uint32_t d = (uint32_t)__cvta_generic_to_shared(dst);
    asm volatile("cp.async.ca.shared.global [%0], [%1], 16;"
                 :: "r"(d), "l"(src));
}

// Scratch (static device arrays; no runtime allocation)
__device__ float g_norm[M_TOK * 128];
__device__ float g_qkv [M_TOK * 384];
__device__ float g_att [M_TOK * 128];
__device__ float g_hid [M_TOK * 512];

// ---------------------------------------------------------------------------
// LayerNorm: one warp per 128-channel row
// ---------------------------------------------------------------------------
__global__ void __launch_bounds__(256) ln_kernel(
    const float* __restrict__ x, const float* __restrict__ w,
    const float* __restrict__ b, float* __restrict__ out)
{
    int lane = threadIdx.x & 31;
    int row  = blockIdx.x * 8 + (threadIdx.x >> 5);
    const float4 v = *(const float4*)(x + (size_t)row * 128 + lane * 4);
    float s = v.x + v.y + v.z + v.w;
    #pragma unroll
    for (int o = 16; o; o >>= 1) s += __shfl_xor_sync(0xffffffffu, s, o);
    float mu = s * (1.0f / 128.0f);
    float dx = v.x - mu, dy = v.y - mu, dz = v.z - mu, dw = v.w - mu;
    float sq = dx * dx + dy * dy + dz * dz + dw * dw;
    #pragma unroll
    for (int o = 16; o; o >>= 1) sq += __shfl_xor_sync(0xffffffffu, sq, o);
    float r = rsqrtf(sq * (1.0f / 128.0f) + 1e-5f);
    float4 wv = *(const float4*)(w + lane * 4);
    float4 bv = *(const float4*)(b + lane * 4);
    float4 o4;
    o4.x = dx * r * wv.x + bv.x;
    o4.y = dy * r * wv.y + bv.y;
    o4.z = dz * r * wv.z + bv.z;
    o4.w = dw * r * wv.w + bv.w;
    *(float4*)(out + (size_t)row * 128 + lane * 4) = o4;
}

// ---------------------------------------------------------------------------
// tf32 tensor-core GEMM with cp.async double buffering.
// CTA 128x64, 8 warps (4x2), warp 32x32 = 2x4 m16n8k8 frags, BK=32.
// Raw fp32 staged (no cvt); mma truncates to tf32 in HW.
// ---------------------------------------------------------------------------
template <bool GELU>
__global__ void __launch_bounds__(256) mma_gemm(
    const float* __restrict__ A, const float* __restrict__ W,
    const float* __restrict__ bias, const float* __restrict__ res,
    float* __restrict__ out, int N, int K)
{
    extern __shared__ float gsm[];
    float* sA = gsm;            // [2][128][36]
    float* sW = gsm + 9216;     // [2][64][36]

    const int tid  = threadIdx.x;
    const int m0   = blockIdx.y << 7, n0 = blockIdx.x << 6;
    const int warp = tid >> 5, lane = tid & 31;
    const int g    = lane >> 2, tig = lane & 3;
    const int wm   = warp >> 1, wn = warp & 1;

    float acc[2][4][4];
    #pragma unroll
    for (int mi = 0; mi < 2; mi++)
        #pragma unroll
        for (int ni = 0; ni < 4; ni++)
            #pragma unroll
            for (int q = 0; q < 4; q++) acc[mi][ni][q] = 0.f;

    const int srow = tid >> 3;        // 0..31
    const int skq  = (tid & 7) << 2;  // 0,4,...,28

    auto stage = [&](int k0, int st) {
        float* dA = sA + st * 4608;
        float* dW = sW + st * 2304;
        #pragma unroll
        for (int p = 0; p < 4; p++)
            cp16(dA + (srow + (p << 5)) * 36 + skq,
                 A + (size_t)(m0 + srow + (p << 5)) * K + k0 + skq);
        #pragma unroll
        for (int p = 0; p < 2; p++)
            cp16(dW + (srow + (p << 5)) * 36 + skq,
                 W + (size_t)(n0 + srow + (p << 5)) * K + k0 + skq);
    };

    stage(0, 0);
    asm volatile("cp.async.commit_group;");

    int s = 0;
    for (int k0 = 0; k0 < K; k0 += 32) {
        const bool more = (k0 + 32 < K);
        if (more) {
            stage(k0 + 32, s ^ 1);
            asm volatile("cp.async.commit_group;");
            asm volatile("cp.async.wait_group 1;");
        } else {
            asm volatile("cp.async.wait_group 0;");
        }
        __syncthreads();

        const float* cA = sA + s * 4608;
        const float* cW = sW + s * 2304;
        #pragma unroll
        for (int k8 = 0; k8 < 32; k8 += 8) {
            uint32_t bf[4][2];
            #pragma unroll
            for (int ni = 0; ni < 4; ni++) {
                int n = (wn << 5) + (ni << 3) + g;
                bf[ni][0] = fu(cW[n * 36 + k8 + tig]);
                bf[ni][1] = fu(cW[n * 36 + k8 + tig + 4]);
            }
            #pragma unroll
            for (int mi = 0; mi < 2; mi++) {
                int m = (wm << 5) + (mi << 4);
                uint32_t a0 = fu(cA[(m + g) * 36 + k8 + tig]);
                uint32_t a1 = fu(cA[(m + g + 8) * 36 + k8 + tig]);
                uint32_t a2 = fu(cA[(m + g) * 36 + k8 + tig + 4]);
                uint32_t a3 = fu(cA[(m + g + 8) * 36 + k8 + tig + 4]);
                #pragma unroll
                for (int ni = 0; ni < 4; ni++)
                    mma8(acc[mi][ni], a0, a1, a2, a3, bf[ni][0], bf[ni][1]);
            }
        }
        __syncthreads();
        s ^= 1;
    }

    #pragma unroll
    for (int mi = 0; mi < 2; mi++) {
        int r0 = m0 + (wm << 5) + (mi << 4) + g;
        int r1 = r0 + 8;
        #pragma unroll
        for (int ni = 0; ni < 4; ni++) {
            int col = n0 + (wn << 5) + (ni << 3) + (tig << 1);
            float b0 = 0.f, b1 = 0.f;
            if (bias) {
                float2 bb = *(const float2*)(bias + col);
                b0 = bb.x; b1 = bb.y;
            }
            float v00 = acc[mi][ni][0] + b0;
            float v01 = acc[mi][ni][1] + b1;
            float v10 = acc[mi][ni][2] + b0;
            float v11 = acc[mi][ni][3] + b1;
            if (GELU) {
                v00 = 0.5f * v00 * (1.0f + erff(v00 * 0.70710678118654752f));
                v01 = 0.5f * v01 * (1.0f + erff(v01 * 0.70710678118654752f));
                v10 = 0.5f * v10 * (1.0f + erff(v10 * 0.70710678118654752f));
                v11 = 0.5f * v11 * (1.0f + erff(v11 * 0.70710678118654752f));
            }
            size_t o0 = (size_t)r0 * N + col;
            size_t o1 = (size_t)r1 * N + col;
            if (res) {
                float2 q0 = *(const float2*)(res + o0);
                float2 q1 = *(const float2*)(res + o1);
                v00 += q0.x; v01 += q0.y;
                v10 += q1.x; v11 += q1.y;
            }
            float2 w0 = {v00, v01};
            float2 w1 = {v10, v11};
            *(float2*)(out + o0) = w0;
            *(float2*)(out + o1) = w1;
        }
    }
}

// ---------------------------------------------------------------------------
// Tensor-core attention + fused LePE. One CTA per (branch, window, head).
// Warp owns 64 Q-rows; loop over 16-key blocks: QK^T mma -> exp in regs ->
// shuffle-transpose P -> P*V mma. O staged to SMEM, then LePE + writeout.
// ---------------------------------------------------------------------------
__global__ void __launch_bounds__(256, 2) attn_kernel(
    const float* __restrict__ qkv,
    const float* __restrict__ cw0, const float* __restrict__ cb0,
    const float* __restrict__ cw1, const float* __restrict__ cb1,
    float* __restrict__ att)
{
    extern __shared__ float dsm[];
    float* sK = dsm;                   // 512 x pitch20
    float* sV = dsm + 512 * 20;        // 512 x 16
    float* sQ = sV + 512 * 16;         // 512 x 16 (prescaled) -> later O
    __shared__ float sCW[27 * 16];
    __shared__ float sCB[16];

    int bid = blockIdx.x;
    int br  = bid >> 8;
    int rem = bid & 255;
    int w   = rem >> 2;
    int n   = rem & 3;
    int b   = w >> 4;
    int tb  = (w >> 3) & 1;
    int hw  = w & 7;
    int tid = threadIdx.x;

    auto tok = [&](int p) -> int {
        int ts = p >> 7, r2 = p & 127;
        if (br == 0) {
            int hs = r2 >> 2, ws = r2 & 3;
            return ((tb * 4 + ts) << 10) + (hs << 5) + (hw << 2) + ws;
        } else {
            int hs = r2 >> 5, ws = r2 & 31;
            return ((tb * 4 + ts) << 10) + (((hw << 2) + hs) << 5) + ws;
        }
    };

    int cq = br * 64 + n * 16;
    int rowbase = b * 8192;

    // stage K (pitch 20), V (pitch 16), Q (pitch 16, *0.25)
    for (int idx = tid; idx < 2048; idx += 256) {
        int p = idx >> 2, c4 = (idx & 3) << 2;
        const float* base = qkv + (size_t)(rowbase + tok(p)) * 384;
        *(float4*)(sK + p * 20 + c4) = *(const float4*)(base + 128 + cq + c4);
        *(float4*)(sV + p * 16 + c4) = *(const float4*)(base + 256 + cq + c4);
        float4 qq = *(const float4*)(base + cq + c4);
        float4 qs = {qq.x * 0.25f, qq.y * 0.25f, qq.z * 0.25f, qq.w * 0.25f};
        *(float4*)(sQ + p * 16 + c4) = qs;
    }
    {
        const float* cw = br ? cw1 : cw0;
        for (int idx = tid; idx < 432; idx += 256) {
            int d = idx / 27, k = idx - d * 27;
            sCW[k * 16 + d] = cw[(n * 16 + d) * 27 + k];
        }
        if (tid < 16) sCB[tid] = (br ? cb1 : cb0)[n * 16 + tid];
    }
    __syncthreads();

    const int lane = tid & 31, warp = tid >> 5;
    const int g = lane >> 2, tig = lane & 3;
    const int qbase = warp << 6;

    // Q fragments (persist)
    uint32_t qf[4][2][4];
    #pragma unroll
    for (int mi = 0; mi < 4; mi++)
        #pragma unroll
        for (int kt = 0; kt < 2; kt++) {
            int r0 = (qbase + (mi << 4) + g) * 16 + (kt << 3) + tig;
            qf[mi][kt][0] = fu(sQ[r0]);
            qf[mi][kt][1] = fu(sQ[r0 + 128]);
            qf[mi][kt][2] = fu(sQ[r0 + 4]);
            qf[mi][kt][3] = fu(sQ[r0 + 132]);
        }

    float acco[4][2][4];
    #pragma unroll
    for (int mi = 0; mi < 4; mi++)
        #pragma unroll
        for (int nt = 0; nt < 2; nt++)
            #pragma unroll
            for (int q = 0; q < 4; q++) acco[mi][nt][q] = 0.f;
    float rs[4][2];
    #pragma unroll
    for (int mi = 0; mi < 4; mi++) { rs[mi][0] = 0.f; rs[mi][1] = 0.f; }

    for (int j0 = 0; j0 < 512; j0 += 16) {
        float sc[4][2][4];
        #pragma unroll
        for (int mi = 0; mi < 4; mi++)
            #pragma unroll
            for (int nt = 0; nt < 2; nt++)
                #pragma unroll
                for (int q = 0; q < 4; q++) sc[mi][nt][q] = 0.f;

        // scores = Q K^T
        #pragma unroll
        for (int nt = 0; nt < 2; nt++) {
            int krow = (j0 + (nt << 3) + g) * 20;
            #pragma unroll
            for (int kt = 0; kt < 2; kt++) {
                uint32_t b0 = fu(sK[krow + (kt << 3) + tig]);
                uint32_t b1 = fu(sK[krow + (kt << 3) + tig + 4]);
                #pragma unroll
                for (int mi = 0; mi < 4; mi++)
                    mma8(sc[mi][nt], qf[mi][kt][0], qf[mi][kt][1],
                         qf[mi][kt][2], qf[mi][kt][3], b0, b1);
            }
        }
        // exp + rowsum (no max-sub: |score| small)
        #pragma unroll
        for (int mi = 0; mi < 4; mi++)
            #pragma unroll
            for (int nt = 0; nt < 2; nt++) {
                float e0 = __expf(sc[mi][nt][0]);
                float e1 = __expf(sc[mi][nt][1]);
                float e2 = __expf(sc[mi][nt][2]);
                float e3 = __expf(sc[mi][nt][3]);
                sc[mi][nt][0] = e0; sc[mi][nt][1] = e1;
                sc[mi][nt][2] = e2; sc[mi][nt][3] = e3;
                rs[mi][0] += e0 + e1;
                rs[mi][1] += e2 + e3;
            }
        // O += P V  (P transposed to A-frags via quad shuffles)
        const int srcl = (lane & ~3) | (tig >> 1);
        const bool odd = tig & 1;
        #pragma unroll
        for (int ktp = 0; ktp < 2; ktp++) {
            uint32_t pa[4][4];
            #pragma unroll
            for (int mi = 0; mi < 4; mi++) {
                float e0 = sc[mi][ktp][0], e1 = sc[mi][ktp][1];
                float e2 = sc[mi][ktp][2], e3 = sc[mi][ktp][3];
                float t0 = __shfl_sync(0xffffffffu, e0, srcl);
                float t1 = __shfl_sync(0xffffffffu, e1, srcl);
                float t2 = __shfl_sync(0xffffffffu, e2, srcl);
                float t3 = __shfl_sync(0xffffffffu, e3, srcl);
                float u0 = __shfl_sync(0xffffffffu, e0, srcl + 2);
                float u1 = __shfl_sync(0xffffffffu, e1, srcl + 2);
                float u2 = __shfl_sync(0xffffffffu, e2, srcl + 2);
                float u3 = __shfl_sync(0xffffffffu, e3, srcl + 2);
                pa[mi][0] = fu(odd ? t1 : t0);   // P[g][tig]
                pa[mi][1] = fu(odd ? t3 : t2);   // P[g+8][tig]
                pa[mi][2] = fu(odd ? u1 : u0);   // P[g][tig+4]
                pa[mi][3] = fu(odd ? u3 : u2);   // P[g+8][tig+4]
            }
            #pragma unroll
            for (int nt = 0; nt < 2; nt++) {
                uint32_t vb0 = fu(sV[(j0 + (ktp << 3) + tig) * 16
                                     + (nt << 3) + g]);
                uint32_t vb1 = fu(sV[(j0 + (ktp << 3) + tig + 4) * 16
                                     + (nt << 3) + g]);
                #pragma unroll
                for (int mi = 0; mi < 4; mi++)
                    mma8(acco[mi][nt], pa[mi][0], pa[mi][1],
                         pa[mi][2], pa[mi][3], vb0, vb1);
            }
        }
    }

    // finalize rowsums across the quad (lanes share g, tig varies)
    #pragma unroll
    for (int mi = 0; mi < 4; mi++) {
        #pragma unroll
        for (int r = 0; r < 2; r++) {
            float v = rs[mi][r];
            v += __shfl_xor_sync(0xffffffffu, v, 1);
            v += __shfl_xor_sync(0xffffffffu, v, 2);
            rs[mi][r] = v;
        }
    }

    // stage O (divided by rowsum) into sQ (all warps done reading Q)
    __syncthreads();
    #pragma unroll
    for (int mi = 0; mi < 4; mi++) {
        float iv0 = 1.0f / rs[mi][0];
        float iv1 = 1.0f / rs[mi][1];
        int row0 = qbase + (mi << 4) + g;
        #pragma unroll
        for (int nt = 0; nt < 2; nt++) {
            int a0 = row0 * 16 + (nt << 3) + (tig << 1);
            float2 lo = {acco[mi][nt][0] * iv0, acco[mi][nt][1] * iv0};
            float2 hi = {acco[mi][nt][2] * iv1, acco[mi][nt][3] * iv1};
            *(float2*)(sQ + a0) = lo;
            *(float2*)(sQ + a0 + 128) = hi;
        }
    }
    __syncthreads();

    // LePE + writeout: 2 rows per thread, O read from sQ, V from sV
    int Hsp = br ? 4 : 32;
    int Wsp = br ? 32 : 4;

    auto write_row = [&](int p) {
        int ltok = tok(p);
        int ts = p >> 7, r2 = p & 127;
        int hs = br ? (r2 >> 5) : (r2 >> 2);
        int ws = r2 & (Wsp - 1);
        float lep[16];
        #pragma unroll
        for (int d = 0; d < 16; d++) lep[d] = sCB[d];
        #pragma unroll
        for (int kt = 0; kt < 3; kt++) {
            int t2 = ts + kt - 1;
            if ((unsigned)t2 >= 4u) continue;
            #pragma unroll
            for (int kh = 0; kh < 3; kh++) {
                int h2 = hs + kh - 1;
                if ((unsigned)h2 >= (unsigned)Hsp) continue;
                #pragma unroll
                for (int kw = 0; kw < 3; kw++) {
                    int w2 = ws + kw - 1;
                    if ((unsigned)w2 >= (unsigned)Wsp) continue;
                    int pp = (t2 * Hsp + h2) * Wsp + w2;
                    int kidx = kt * 9 + kh * 3 + kw;
                    const float4* wr4 = (const float4*)&sCW[kidx * 16];
                    const float4* vr4 = (const float4*)&sV[pp * 16];
                    #pragma unroll
                    for (int d4 = 0; d4 < 4; d4++) {
                        float4 wv = wr4[d4];
                        float4 vv = vr4[d4];
                        lep[d4*4+0] = fmaf(wv.x, vv.x, lep[d4*4+0]);
                        lep[d4*4+1] = fmaf(wv.y, vv.y, lep[d4*4+1]);
                        lep[d4*4+2] = fmaf(wv.z, vv.z, lep[d4*4+2]);
                        lep[d4*4+3] = fmaf(wv.w, vv.w, lep[d4*4+3]);
                    }
                }
            }
        }
        float* op = att + (size_t)(rowbase + ltok) * 128 + cq;
        const float4* ov = (const float4*)(sQ + p * 16);
        #pragma unroll
        for (int d4 = 0; d4 < 4; d4++) {
            float4 a = ov[d4];
            float4 o;
            o.x = a.x + lep[d4*4+0];
            o.y = a.y + lep[d4*4+1];
            o.z = a.z + lep[d4*4+2];
            o.w = a.w + lep[d4*4+3];
            *(float4*)(op + d4 * 4) = o;
        }
    };
    write_row(tid);
    write_row(tid + 256);
}

// ---------------------------------------------------------------------------
// Launch sequence
// ---------------------------------------------------------------------------
extern "C" void kernel_launch(void* const* d_in, const int* in_sizes, int n_in,
                              void* d_out, int out_size)
{
    const float* x    = (const float*)d_in[0];
    const float* n1w  = (const float*)d_in[1];
    const float* n1b  = (const float*)d_in[2];
    const float* qkvw = (const float*)d_in[3];
    const float* cw0  = (const float*)d_in[4];
    const float* cb0  = (const float*)d_in[5];
    const float* cw1  = (const float*)d_in[6];
    const float* cb1  = (const float*)d_in[7];
    const float* pw   = (const float*)d_in[8];
    const float* pb   = (const float*)d_in[9];
    const float* n2w  = (const float*)d_in[10];
    const float* n2b  = (const float*)d_in[11];
    const float* f1w  = (const float*)d_in[12];
    const float* f1b  = (const float*)d_in[13];
    const float* f2w  = (const float*)d_in[14];
    const float* f2b  = (const float*)d_in[15];
    float* out = (float*)d_out;

    float *pnorm, *pqkv, *patt, *phid;
    cudaGetSymbolAddress((void**)&pnorm, g_norm);
    cudaGetSymbolAddress((void**)&pqkv,  g_qkv);
    cudaGetSymbolAddress((void**)&patt,  g_att);
    cudaGetSymbolAddress((void**)&phid,  g_hid);

    const int ATTN_SMEM = (512 * 20 + 512 * 16 + 512 * 16) * 4;  // 106496
    const int GEMM_SMEM = (2 * 128 * 36 + 2 * 64 * 36) * 4;      // 55296
    cudaFuncSetAttribute(attn_kernel,
                         cudaFuncAttributeMaxDynamicSharedMemorySize, ATTN_SMEM);
    cudaFuncSetAttribute(mma_gemm<false>,
                         cudaFuncAttributeMaxDynamicSharedMemorySize, GEMM_SMEM);
    cudaFuncSetAttribute(mma_gemm<true>,
                         cudaFuncAttributeMaxDynamicSharedMemorySize, GEMM_SMEM);

    // 1) LN1
    ln_kernel<<<4096, 256>>>(x, n1w, n1b, pnorm);
    // 2) qkv = LN1(x) @ qkv_w^T   (M x 384)
    mma_gemm<false><<<dim3(6, 256), 256, GEMM_SMEM>>>(pnorm, qkvw, nullptr,
                                                      nullptr, pqkv, 384, 128);
    // 3) windowed attention + LePE, both branches
    attn_kernel<<<512, 256, ATTN_SMEM>>>(pqkv, cw0, cb0, cw1, cb1, patt);
    // 4) x2 = x + att @ proj_w^T + proj_b  -> d_out
    mma_gemm<false><<<dim3(2, 256), 256, GEMM_SMEM>>>(patt, pw, pb, x, out,
                                                      128, 128);
    // 5) LN2
    ln_kernel<<<4096, 256>>>(out, n2w, n2b, pnorm);
    // 6) hid = gelu(LN2 @ fc1_w^T + fc1_b)  (M x 512)
    mma_gemm<true><<<dim3(8, 256), 256, GEMM_SMEM>>>(pnorm, f1w, f1b, nullptr,
                                                     phid, 512, 128);
    // 7) out = x2 + hid @ fc2_w^T + fc2_b
    mma_gemm<false><<<dim3(2, 256), 256, GEMM_SMEM>>>(phid, f2w, f2b, out, out,
                                                      128, 512);
}